// round 7
// baseline (speedup 1.0000x reference)
#include <cuda_runtime.h>
#include <cuda_bf16.h>
#include <math.h>
#include <stdint.h>

#define NBANDS 160
#define NROWS  96
#define TLEN   2048
#define HALF_T 1024
#define NTRIL  4560   // 96*95/2
#define SORTN  8192

// ---------------- scratch (static device globals; no allocation) ----------------
__device__ float  g_xc[(size_t)NBANDS * NROWS * TLEN];    // centered rows (fp32)
__device__ double g_norm2[(size_t)NBANDS * NROWS];        // ||Xc||^2 in fp64
__device__ float  g_C[(size_t)NBANDS * NROWS * NROWS];    // correlation matrices
__device__ float  g_feat[(size_t)NBANDS * 5 * NROWS];     // per-row 5 features
__device__ float2 g_tw[HALF_T];                           // exp(-2*pi*i*k/2048)

// ---------------- generic reductions (used by post kernel) ----------------
__device__ __forceinline__ float blockReduceSum(float val, float* red) {
    __syncthreads();
    int lane = threadIdx.x & 31, wid = threadIdx.x >> 5;
    #pragma unroll
    for (int o = 16; o > 0; o >>= 1) val += __shfl_xor_sync(0xffffffffu, val, o);
    if (lane == 0) red[wid] = val;
    __syncthreads();
    if (wid == 0) {
        int nw = (blockDim.x + 31) >> 5;
        float v = (lane < nw) ? red[lane] : 0.f;
        #pragma unroll
        for (int o = 16; o > 0; o >>= 1) v += __shfl_xor_sync(0xffffffffu, v, o);
        if (lane == 0) red[0] = v;
    }
    __syncthreads();
    return red[0];
}

// ---------------- batched reductions for stats kernel (256 threads = 8 warps) ----------------
__device__ __forceinline__ void reduce4D(double& a, double& b, double& c, double& d, double* buf) {
    int lane = threadIdx.x & 31, wid = threadIdx.x >> 5;
    #pragma unroll
    for (int o = 16; o > 0; o >>= 1) {
        a += __shfl_xor_sync(0xffffffffu, a, o);
        b += __shfl_xor_sync(0xffffffffu, b, o);
        c += __shfl_xor_sync(0xffffffffu, c, o);
        d += __shfl_xor_sync(0xffffffffu, d, o);
    }
    if (lane == 0) { buf[wid*4+0]=a; buf[wid*4+1]=b; buf[wid*4+2]=c; buf[wid*4+3]=d; }
    __syncthreads();
    if (threadIdx.x == 0) {
        double ta=0, tb=0, tc=0, td=0;
        #pragma unroll
        for (int w = 0; w < 8; w++) { ta+=buf[w*4+0]; tb+=buf[w*4+1]; tc+=buf[w*4+2]; td+=buf[w*4+3]; }
        buf[0]=ta; buf[1]=tb; buf[2]=tc; buf[3]=td;
    }
    __syncthreads();
    a=buf[0]; b=buf[1]; c=buf[2]; d=buf[3];
    __syncthreads();
}

__device__ __forceinline__ void reduce2D(double& a, double& b, double* buf) {
    int lane = threadIdx.x & 31, wid = threadIdx.x >> 5;
    #pragma unroll
    for (int o = 16; o > 0; o >>= 1) {
        a += __shfl_xor_sync(0xffffffffu, a, o);
        b += __shfl_xor_sync(0xffffffffu, b, o);
    }
    if (lane == 0) { buf[wid*2+0]=a; buf[wid*2+1]=b; }
    __syncthreads();
    if (threadIdx.x == 0) {
        double ta=0, tb=0;
        #pragma unroll
        for (int w = 0; w < 8; w++) { ta+=buf[w*2+0]; tb+=buf[w*2+1]; }
        buf[0]=ta; buf[1]=tb;
    }
    __syncthreads();
    a=buf[0]; b=buf[1];
    __syncthreads();
}

__device__ __forceinline__ void reduceMax2(float& a, float& b, float* buf) {
    int lane = threadIdx.x & 31, wid = threadIdx.x >> 5;
    #pragma unroll
    for (int o = 16; o > 0; o >>= 1) {
        a = fmaxf(a, __shfl_xor_sync(0xffffffffu, a, o));
        b = fmaxf(b, __shfl_xor_sync(0xffffffffu, b, o));
    }
    if (lane == 0) { buf[wid*2+0]=a; buf[wid*2+1]=b; }
    __syncthreads();
    if (threadIdx.x == 0) {
        float ta=-INFINITY, tb=-INFINITY;
        #pragma unroll
        for (int w = 0; w < 8; w++) { ta=fmaxf(ta,buf[w*2+0]); tb=fmaxf(tb,buf[w*2+1]); }
        buf[0]=ta; buf[1]=tb;
    }
    __syncthreads();
    a=buf[0]; b=buf[1];
    __syncthreads();
}

// ---------------- kernel 0: twiddle table ----------------
__global__ void init_tw_kernel() {
    int k = blockIdx.x * 256 + threadIdx.x;
    if (k < HALF_T) {
        float sv, cv;
        sincospif(-(float)k / 1024.0f, &sv, &cv);
        g_tw[k] = make_float2(cv, sv);
    }
}

// ---------------- kernel 1: stats + center + packed 2-row Stockham FFT + entropy ----------------
// grid (48, 160), block 256. Rows 2*rp and 2*rp+1 packed as re/im of one complex FFT.
__global__ void stats_fft_kernel(const float* __restrict__ wc) {
    const int rp = blockIdx.x;
    const int band = blockIdx.y;
    const int b = band / 5, nb = band % 5;
    const int r0 = 2 * rp, r1 = r0 + 1;
    const float* __restrict__ x = wc + (((size_t)b * NROWS + r0) * 5 + nb) * TLEN;
    const float* __restrict__ y = wc + (((size_t)b * NROWS + r1) * 5 + nb) * TLEN;

    __shared__ float2 bufA[TLEN];
    __shared__ float2 bufB[TLEN];
    __shared__ double redd[32];
    __shared__ float  redf[16];

    const int tid = threadIdx.x;

    float vx[8], vy[8];
    double sx = 0.0, sqx = 0.0, sy = 0.0, sqy = 0.0;
    float mxx = 0.f, mxy = 0.f;
    #pragma unroll
    for (int k = 0; k < 8; k++) {
        float a = x[tid + 256 * k];
        float c = y[tid + 256 * k];
        vx[k] = a; vy[k] = c;
        sx += (double)a; sqx += (double)a * (double)a; mxx = fmaxf(mxx, fabsf(a));
        sy += (double)c; sqy += (double)c * (double)c; mxy = fmaxf(mxy, fabsf(c));
        bufA[tid + 256 * k] = make_float2(a, c);
    }

    reduce4D(sx, sy, sqx, sqy, redd);   // totals now in all threads
    reduceMax2(mxx, mxy, redf);
    float meanx = (float)(sx / (double)TLEN);
    float meany = (float)(sy / (double)TLEN);

    double nx = 0.0, ny = 0.0;
    float cx[8], cy[8];
    #pragma unroll
    for (int k = 0; k < 8; k++) {
        cx[k] = vx[k] - meanx; nx += (double)cx[k] * (double)cx[k];
        cy[k] = vy[k] - meany; ny += (double)cy[k] * (double)cy[k];
    }
    reduce2D(nx, ny, redd);

    float* __restrict__ xc0 = g_xc + ((size_t)band * NROWS + r0) * TLEN;
    float* __restrict__ xc1 = g_xc + ((size_t)band * NROWS + r1) * TLEN;
    #pragma unroll
    for (int k = 0; k < 8; k++) {
        xc0[tid + 256 * k] = cx[k];
        xc1[tid + 256 * k] = cy[k];
    }
    if (tid == 0) {
        g_norm2[(size_t)band * NROWS + r0] = nx;
        g_norm2[(size_t)band * NROWS + r1] = ny;
    }

    // ---- Stockham autosort radix-2 FFT (natural in, natural out) ----
    float2* src = bufA;
    float2* dst = bufB;
    #pragma unroll 1
    for (int s = 0; s < 11; s++) {
        const int l = 1 << s;
        __syncthreads();
        #pragma unroll
        for (int ti = 0; ti < 4; ti++) {
            int t = tid + 256 * ti;
            int j = t & (l - 1);
            int i = t >> s;
            float2 u = src[t];
            float2 v = src[t + HALF_T];
            float2 w = g_tw[j << (10 - s)];
            float vr = v.x * w.x - v.y * w.y;
            float vi = v.x * w.y + v.y * w.x;
            int o = t + i * l;
            dst[o]     = make_float2(u.x + vr, u.y + vi);
            dst[o + l] = make_float2(u.x - vr, u.y - vi);
        }
        float2* tmp = src; src = dst; dst = tmp;
    }
    __syncthreads();
    // result in src, natural order. Unpack two real spectra.

    double psx = 0.0, psy = 0.0;
    float pxv[4], pyv[4];
    #pragma unroll
    for (int ki = 0; ki < 4; ki++) {
        int k = tid + 256 * ki;
        float2 Zk = src[k];
        float2 Zn = src[(TLEN - k) & (TLEN - 1)];
        float Xr = 0.5f * (Zk.x + Zn.x);
        float Xi = 0.5f * (Zk.y - Zn.y);
        float Yr = 0.5f * (Zk.y + Zn.y);
        float Yi = 0.5f * (Zn.x - Zk.x);
        float px = Xr * Xr + Xi * Xi;
        float py = Yr * Yr + Yi * Yi;
        pxv[ki] = px; pyv[ki] = py;
        psx += (double)px; psy += (double)py;
    }
    reduce2D(psx, psy, redd);
    double Sdx = (psx == 0.0) ? 1.0 : psx;
    double Sdy = (psy == 0.0) ? 1.0 : psy;

    double ex = 0.0, ey = 0.0;
    #pragma unroll
    for (int ki = 0; ki < 4; ki++) {
        float p0 = (float)((double)pxv[ki] / Sdx);
        float p1 = (float)((double)pyv[ki] / Sdy);
        ex += (double)(p0 * logf(p0 + 1e-10f));
        ey += (double)(p1 * logf(p1 + 1e-10f));
    }
    reduce2D(ex, ey, redd);

    if (tid == 0) {
        float* f = g_feat + (size_t)band * 5 * NROWS;
        f[0 * NROWS + r0] = meanx;
        f[1 * NROWS + r0] = (float)sqrt(nx / (double)(TLEN - 1));
        f[2 * NROWS + r0] = (float)sqx;
        f[3 * NROWS + r0] = mxx;
        f[4 * NROWS + r0] = (float)(-ex);
        f[0 * NROWS + r1] = meany;
        f[1 * NROWS + r1] = (float)sqrt(ny / (double)(TLEN - 1));
        f[2 * NROWS + r1] = (float)sqy;
        f[3 * NROWS + r1] = mxy;
        f[4 * NROWS + r1] = (float)(-ey);
    }
}

// ---------------- kernel 2: correlation GEMM, float4 smem, 6x6 tile, 128 threads ----------------
// grid (2, 160). Block (half, band) computes rows [48*half, 48*half+48) x all 96 cols.
#define TK 64
#define STRIDE 68
__global__ void corr_kernel() {
    const int band = blockIdx.y;
    const int half = blockIdx.x;
    __shared__ float st[NROWS][STRIDE];   // row-major, k contiguous
    __shared__ double n2s[NROWS];
    const float* __restrict__ Xb = g_xc + (size_t)band * NROWS * TLEN;

    const int tid = threadIdx.x;         // 128 threads
    const int tx = tid & 15;             // 0..15
    const int ty = tid >> 4;             // 0..7
    const int rbase = half * 48;

    if (tid < NROWS) n2s[tid] = g_norm2[(size_t)band * NROWS + tid];

    double accd[6][6];
    #pragma unroll
    for (int u = 0; u < 6; u++)
        #pragma unroll
        for (int w = 0; w < 6; w++) accd[u][w] = 0.0;

    for (int kt = 0; kt < TLEN; kt += TK) {
        // load 96 rows x 64 floats
        #pragma unroll
        for (int it = 0; it < 12; it++) {
            int idx = tid + 128 * it;     // 0..1535
            int r = idx >> 4, q = idx & 15;
            float4 g = *reinterpret_cast<const float4*>(Xb + (size_t)r * TLEN + kt + 4 * q);
            *reinterpret_cast<float4*>(&st[r][4 * q]) = g;
        }
        __syncthreads();

        float acc[6][6];
        #pragma unroll
        for (int u = 0; u < 6; u++)
            #pragma unroll
            for (int w = 0; w < 6; w++) acc[u][w] = 0.f;

        #pragma unroll 4
        for (int k4 = 0; k4 < 16; k4++) {
            float4 a4[6], b4[6];
            #pragma unroll
            for (int u = 0; u < 6; u++)
                a4[u] = *reinterpret_cast<const float4*>(&st[rbase + ty + 8 * u][4 * k4]);
            #pragma unroll
            for (int w = 0; w < 6; w++)
                b4[w] = *reinterpret_cast<const float4*>(&st[tx + 16 * w][4 * k4]);
            #pragma unroll
            for (int u = 0; u < 6; u++)
                #pragma unroll
                for (int w = 0; w < 6; w++) {
                    acc[u][w] = fmaf(a4[u].x, b4[w].x, acc[u][w]);
                    acc[u][w] = fmaf(a4[u].y, b4[w].y, acc[u][w]);
                    acc[u][w] = fmaf(a4[u].z, b4[w].z, acc[u][w]);
                    acc[u][w] = fmaf(a4[u].w, b4[w].w, acc[u][w]);
                }
        }
        __syncthreads();

        #pragma unroll
        for (int u = 0; u < 6; u++)
            #pragma unroll
            for (int w = 0; w < 6; w++) accd[u][w] += (double)acc[u][w];
    }

    float* __restrict__ Cb = g_C + (size_t)band * NROWS * NROWS;
    #pragma unroll
    for (int u = 0; u < 6; u++) {
        int r = rbase + ty + 8 * u;
        double ni = sqrt(n2s[r]);
        if (ni == 0.0) ni = 1.0;
        #pragma unroll
        for (int w = 0; w < 6; w++) {
            int c = tx + 16 * w;
            double nj = sqrt(n2s[c]);
            if (nj == 0.0) nj = 1.0;
            double val = accd[u][w] / (ni * nj);
            Cb[r * NROWS + c] = (r == c) ? 0.f : (float)val;
        }
    }
}

// ---------------- kernel 3: quantile (bitonic sort) + mask + graph props + MLP ----------------
// grid 160, block 1024
__global__ void post_kernel(const int* __restrict__ community,
                            const float* __restrict__ W1, const float* __restrict__ b1,
                            const float* __restrict__ W2, const float* __restrict__ b2,
                            float* __restrict__ outA, float* __restrict__ outF) {
    __shared__ float s[SORTN];
    __shared__ unsigned bits[NROWS][3];
    __shared__ float degf[NROWS];
    __shared__ int comm[NROWS];
    __shared__ float red[32];
    __shared__ float feat11[11];
    __shared__ float h[32];
    __shared__ float sprops[6];
    __shared__ float s_thr;

    const int band = blockIdx.x;
    const int tid = threadIdx.x;
    const float* __restrict__ Cb = g_C + (size_t)band * NROWS * NROWS;
    float* __restrict__ Ao = outA + (size_t)band * NROWS * NROWS;

    // ---- load |C| lower triangle, pad with +inf ----
    for (int i = tid; i < SORTN; i += 1024) s[i] = INFINITY;
    __syncthreads();
    for (int idx = tid; idx < NROWS * NROWS; idx += 1024) {
        int i = idx / NROWS, j = idx - i * NROWS;
        if (j < i) s[i * (i - 1) / 2 + j] = fabsf(Cb[idx]);
    }

    // ---- bitonic sort ----
    for (int k = 2; k <= SORTN; k <<= 1) {
        for (int j = k >> 1; j > 0; j >>= 1) {
            __syncthreads();
            #pragma unroll 1
            for (int i = tid; i < SORTN; i += 1024) {
                int ixj = i ^ j;
                if (ixj > i) {
                    float a = s[i], bv = s[ixj];
                    bool up = ((i & k) == 0);
                    if ((a > bv) == up) { s[i] = bv; s[ixj] = a; }
                }
            }
        }
    }
    __syncthreads();
    if (tid == 0) {
        double pos = 0.8 * (double)(NTRIL - 1);     // 3647.2
        int lo = (int)pos;
        double fr = pos - (double)lo;
        s_thr = (float)((double)s[lo] + fr * ((double)s[lo + 1] - (double)s[lo]));
    }
    if (tid < NROWS) comm[tid] = community[tid];
    __syncthreads();
    const float thr = s_thr;

    // ---- A write (all 1024 threads) ----
    #pragma unroll 1
    for (int idx = tid; idx < NROWS * NROWS; idx += 1024) {
        int row = idx / NROWS, col = idx - row * NROWS;
        float c = Cb[idx];
        bool keep = (fabsf(c) >= thr) && (row != col);
        Ao[idx] = keep ? c : 0.f;
    }

    // ---- adjacency bitmasks + degree (tid < 96) ----
    int mydeg = 0;
    if (tid < NROWS) {
        unsigned b0 = 0, b1w = 0, b2w = 0;
        const float* crow = Cb + tid * NROWS;
        #pragma unroll 4
        for (int j = 0; j < NROWS; j++) {
            float c = crow[j];
            bool keep = (fabsf(c) >= thr) && (j != tid);
            if (keep) {
                mydeg++;
                if (j < 32) b0 |= 1u << j;
                else if (j < 64) b1w |= 1u << (j - 32);
                else b2w |= 1u << (j - 64);
            }
        }
        bits[tid][0] = b0; bits[tid][1] = b1w; bits[tid][2] = b2w;
        degf[tid] = (float)mydeg;
    }
    __syncthreads();

    float degsum = blockReduceSum(tid < NROWS ? (float)mydeg : 0.f, red);
    float ne = 0.5f * degsum;

    float cnt = 0.f;
    if (tid < NROWS) {
        unsigned r0 = bits[tid][0], r1 = bits[tid][1], r2 = bits[tid][2];
        int c6 = 0;
        #pragma unroll 1
        for (int w = 0; w < 3; w++) {
            unsigned mw = bits[tid][w];
            while (mw) {
                int j = __ffs(mw) - 1 + 32 * w;
                mw &= mw - 1;
                c6 += __popc(r0 & bits[j][0]) + __popc(r1 & bits[j][1]) + __popc(r2 & bits[j][2]);
            }
        }
        cnt = (float)c6;
    }
    float tri6 = blockReduceSum(cnt, red);
    float tri = tri6 / 6.0f;

    float pp = (tid < NROWS) ? ((float)mydeg * ((float)mydeg - 1.0f)) : 0.f;
    float poss = blockReduceSum(pp, red) * 0.5f;

    float m2 = 2.0f * ne;
    float m2s = (m2 > 0.f) ? m2 : 1.0f;
    float macc = 0.f;
    if (tid < NROWS) {
        int ci = comm[tid];
        float di = (float)mydeg;
        #pragma unroll 2
        for (int j = 0; j < NROWS; j++) {
            if (j != tid && comm[j] == ci) {
                float bij = (float)((bits[tid][j >> 5] >> (j & 31)) & 1u);
                macc += bij - di * degf[j] / m2s;
            }
        }
    }
    float modsum = blockReduceSum(macc, red);
    float mod = (m2 > 0.f) ? (modsum / m2s) : 0.f;

    if (tid < 5) {
        const float* f = g_feat + (size_t)band * 5 * NROWS + tid * NROWS;
        float sm = 0.f;
        for (int r = 0; r < NROWS; r++) sm += f[r];
        feat11[tid] = sm / (float)NROWS;
    }
    if (tid == 0) {
        float n = (float)NROWS;
        sprops[0] = ne;
        sprops[1] = ne / (n * (n - 1.0f) * 0.5f);
        sprops[2] = degsum / n;
        sprops[3] = (poss > 0.f) ? (tri / poss) : 0.f;
        sprops[4] = (n + 2.0f * ne) / (n * (n - 1.0f));
        sprops[5] = mod;
    }
    __syncthreads();
    if (tid < 6) feat11[5 + tid] = sprops[tid];
    __syncthreads();

    if (tid < 32) {
        float acc = b1[tid];
        #pragma unroll
        for (int k = 0; k < 11; k++) acc = fmaf(feat11[k], W1[tid * 11 + k], acc);
        h[tid] = fmaxf(acc, 0.f);
    }
    __syncthreads();
    if (tid < 64) {
        float acc = b2[tid];
        #pragma unroll
        for (int k = 0; k < 32; k++) acc = fmaf(h[k], W2[tid * 32 + k], acc);
        outF[(size_t)band * 64 + tid] = acc;
    }
}

// ---------------- launch ----------------
extern "C" void kernel_launch(void* const* d_in, const int* in_sizes, int n_in,
                              void* d_out, int out_size) {
    const float* wc        = (const float*)d_in[0];
    const int*   community = (const int*)d_in[2];
    const float* W1        = (const float*)d_in[3];
    const float* b1        = (const float*)d_in[4];
    const float* W2        = (const float*)d_in[5];
    const float* b2        = (const float*)d_in[6];

    float* out = (float*)d_out;
    float* outA = out;                                   // 32*5*96*96
    float* outF = out + (size_t)NBANDS * NROWS * NROWS;  // 32*5*64

    init_tw_kernel<<<4, 256>>>();
    dim3 gS(NROWS / 2, NBANDS);
    stats_fft_kernel<<<gS, 256>>>(wc);
    dim3 gC(2, NBANDS);
    corr_kernel<<<gC, 128>>>();
    post_kernel<<<NBANDS, 1024>>>(community, W1, b1, W2, b2, outA, outF);
}

// round 8
// speedup vs baseline: 3.1067x; 3.1067x over previous
#include <cuda_runtime.h>
#include <cuda_bf16.h>
#include <math.h>
#include <stdint.h>

#define NBANDS 160
#define NROWS  96
#define TLEN   2048
#define HALF_T 1024
#define NTRIL  4560   // 96*95/2

// ---------------- scratch (static device globals; no allocation) ----------------
__device__ float  g_xc[(size_t)NBANDS * NROWS * TLEN];    // centered rows (fp32)
__device__ double g_norm2[(size_t)NBANDS * NROWS];        // ||Xc||^2 (exact via df)
__device__ float  g_C[(size_t)NBANDS * NROWS * NROWS];    // correlation matrices
__device__ float  g_feat[(size_t)NBANDS * 5 * NROWS];     // per-row 5 features
__device__ float2 g_tw[HALF_T];                           // exp(-2*pi*i*k/2048)

// ---------------- two-float compensated add (fp32 pipe only) ----------------
__device__ __forceinline__ void twosum_acc(float& hi, float& lo, float a) {
    float s  = hi + a;
    float bb = s - hi;
    float e  = (hi - (s - bb)) + (a - bb);
    hi = s; lo += e;
}

// ---------------- generic fp32 block reduce (any blockDim multiple of 32) ----------------
__device__ __forceinline__ float blockReduceSum(float val, float* red) {
    __syncthreads();
    int lane = threadIdx.x & 31, wid = threadIdx.x >> 5;
    #pragma unroll
    for (int o = 16; o > 0; o >>= 1) val += __shfl_xor_sync(0xffffffffu, val, o);
    if (lane == 0) red[wid] = val;
    __syncthreads();
    if (wid == 0) {
        int nw = (blockDim.x + 31) >> 5;
        float v = (lane < nw) ? red[lane] : 0.f;
        #pragma unroll
        for (int o = 16; o > 0; o >>= 1) v += __shfl_xor_sync(0xffffffffu, v, o);
        if (lane == 0) red[0] = v;
    }
    __syncthreads();
    return red[0];
}

// ---------------- batched fp32 reductions for stats kernel (256 thr, 8 warps) ----------------
__device__ __forceinline__ void red4f(float& a, float& b, float& c, float& d, float* buf) {
    int lane = threadIdx.x & 31, wid = threadIdx.x >> 5;
    #pragma unroll
    for (int o = 16; o > 0; o >>= 1) {
        a += __shfl_xor_sync(0xffffffffu, a, o);
        b += __shfl_xor_sync(0xffffffffu, b, o);
        c += __shfl_xor_sync(0xffffffffu, c, o);
        d += __shfl_xor_sync(0xffffffffu, d, o);
    }
    if (lane == 0) { buf[wid*4+0]=a; buf[wid*4+1]=b; buf[wid*4+2]=c; buf[wid*4+3]=d; }
    __syncthreads();
    if (threadIdx.x == 0) {
        float ta=0, tb=0, tc=0, td=0;
        #pragma unroll
        for (int w = 0; w < 8; w++) { ta+=buf[w*4+0]; tb+=buf[w*4+1]; tc+=buf[w*4+2]; td+=buf[w*4+3]; }
        buf[0]=ta; buf[1]=tb; buf[2]=tc; buf[3]=td;
    }
    __syncthreads();
    a=buf[0]; b=buf[1]; c=buf[2]; d=buf[3];
    __syncthreads();
}

__device__ __forceinline__ void red2f(float& a, float& b, float* buf) {
    int lane = threadIdx.x & 31, wid = threadIdx.x >> 5;
    #pragma unroll
    for (int o = 16; o > 0; o >>= 1) {
        a += __shfl_xor_sync(0xffffffffu, a, o);
        b += __shfl_xor_sync(0xffffffffu, b, o);
    }
    if (lane == 0) { buf[wid*2+0]=a; buf[wid*2+1]=b; }
    __syncthreads();
    if (threadIdx.x == 0) {
        float ta=0, tb=0;
        #pragma unroll
        for (int w = 0; w < 8; w++) { ta+=buf[w*2+0]; tb+=buf[w*2+1]; }
        buf[0]=ta; buf[1]=tb;
    }
    __syncthreads();
    a=buf[0]; b=buf[1];
    __syncthreads();
}

__device__ __forceinline__ void redmax2f(float& a, float& b, float* buf) {
    int lane = threadIdx.x & 31, wid = threadIdx.x >> 5;
    #pragma unroll
    for (int o = 16; o > 0; o >>= 1) {
        a = fmaxf(a, __shfl_xor_sync(0xffffffffu, a, o));
        b = fmaxf(b, __shfl_xor_sync(0xffffffffu, b, o));
    }
    if (lane == 0) { buf[wid*2+0]=a; buf[wid*2+1]=b; }
    __syncthreads();
    if (threadIdx.x == 0) {
        float ta=-INFINITY, tb=-INFINITY;
        #pragma unroll
        for (int w = 0; w < 8; w++) { ta=fmaxf(ta,buf[w*2+0]); tb=fmaxf(tb,buf[w*2+1]); }
        buf[0]=ta; buf[1]=tb;
    }
    __syncthreads();
    a=buf[0]; b=buf[1];
    __syncthreads();
}

// df (two-float) reduce for two accumulators: exact to ~2^-48
__device__ __forceinline__ void red2df(float& ahi, float& alo, float& bhi, float& blo, float* buf) {
    int lane = threadIdx.x & 31, wid = threadIdx.x >> 5;
    #pragma unroll
    for (int o = 16; o > 0; o >>= 1) {
        float ohi = __shfl_xor_sync(0xffffffffu, ahi, o);
        float olo = __shfl_xor_sync(0xffffffffu, alo, o);
        float s = ahi + ohi; float bb = s - ahi;
        float e = (ahi - (s - bb)) + (ohi - bb);
        alo = alo + olo + e; ahi = s;
        ohi = __shfl_xor_sync(0xffffffffu, bhi, o);
        olo = __shfl_xor_sync(0xffffffffu, blo, o);
        s = bhi + ohi; bb = s - bhi;
        e = (bhi - (s - bb)) + (ohi - bb);
        blo = blo + olo + e; bhi = s;
    }
    if (lane == 0) { buf[wid*4+0]=ahi; buf[wid*4+1]=alo; buf[wid*4+2]=bhi; buf[wid*4+3]=blo; }
    __syncthreads();
    if (threadIdx.x == 0) {
        float thi=0, tlo=0;
        #pragma unroll
        for (int w = 0; w < 8; w++) {
            twosum_acc(thi, tlo, buf[w*4+0]);
            tlo += buf[w*4+1];
        }
        buf[0]=thi; buf[1]=tlo;
        thi=0; tlo=0;
        #pragma unroll
        for (int w = 0; w < 8; w++) {
            twosum_acc(thi, tlo, buf[w*4+2]);
            tlo += buf[w*4+3];
        }
        buf[2]=thi; buf[3]=tlo;
    }
    __syncthreads();
    ahi=buf[0]; alo=buf[1]; bhi=buf[2]; blo=buf[3];
    __syncthreads();
}

// ---------------- kernel 0: twiddle table ----------------
__global__ void init_tw_kernel() {
    int k = blockIdx.x * 256 + threadIdx.x;
    if (k < HALF_T) {
        float sv, cv;
        sincospif(-(float)k / 1024.0f, &sv, &cv);
        g_tw[k] = make_float2(cv, sv);
    }
}

// ---------------- kernel 1: stats + center + packed 2-row Stockham FFT + entropy ----------------
// grid (48, 160), block 256. Rows 2*rp and 2*rp+1 packed as re/im of one complex FFT.
// All fp32 except: exact df for norm2, one fp64 store per row at tid==0.
__global__ void stats_fft_kernel(const float* __restrict__ wc) {
    const int rp = blockIdx.x;
    const int band = blockIdx.y;
    const int b = band / 5, nb = band % 5;
    const int r0 = 2 * rp, r1 = r0 + 1;
    const float* __restrict__ x = wc + (((size_t)b * NROWS + r0) * 5 + nb) * TLEN;
    const float* __restrict__ y = wc + (((size_t)b * NROWS + r1) * 5 + nb) * TLEN;

    __shared__ float2 bufA[TLEN];
    __shared__ float2 bufB[TLEN];
    __shared__ float  redf[32];

    const int tid = threadIdx.x;

    float vx[8], vy[8];
    float sx = 0.f, sqx = 0.f, sy = 0.f, sqy = 0.f;
    float mxx = 0.f, mxy = 0.f;
    #pragma unroll
    for (int k = 0; k < 8; k++) {
        float a = x[tid + 256 * k];
        float c = y[tid + 256 * k];
        vx[k] = a; vy[k] = c;
        sx += a; sqx = fmaf(a, a, sqx); mxx = fmaxf(mxx, fabsf(a));
        sy += c; sqy = fmaf(c, c, sqy); mxy = fmaxf(mxy, fabsf(c));
        bufA[tid + 256 * k] = make_float2(a, c);
    }

    red4f(sx, sy, sqx, sqy, redf);
    redmax2f(mxx, mxy, redf);
    float meanx = sx / (float)TLEN;
    float meany = sy / (float)TLEN;

    // centered rows; exact df norm2
    float nxh = 0.f, nxl = 0.f, nyh = 0.f, nyl = 0.f;
    float cx[8], cy[8];
    #pragma unroll
    for (int k = 0; k < 8; k++) {
        cx[k] = vx[k] - meanx; twosum_acc(nxh, nxl, cx[k] * cx[k]);
        cy[k] = vy[k] - meany; twosum_acc(nyh, nyl, cy[k] * cy[k]);
    }
    red2df(nxh, nxl, nyh, nyl, redf);

    float* __restrict__ xc0 = g_xc + ((size_t)band * NROWS + r0) * TLEN;
    float* __restrict__ xc1 = g_xc + ((size_t)band * NROWS + r1) * TLEN;
    #pragma unroll
    for (int k = 0; k < 8; k++) {
        xc0[tid + 256 * k] = cx[k];
        xc1[tid + 256 * k] = cy[k];
    }
    if (tid == 0) {
        double n2x = (double)nxh + (double)nxl;
        double n2y = (double)nyh + (double)nyl;
        g_norm2[(size_t)band * NROWS + r0] = n2x;
        g_norm2[(size_t)band * NROWS + r1] = n2y;
        float* f = g_feat + (size_t)band * 5 * NROWS;
        f[0 * NROWS + r0] = meanx;
        f[1 * NROWS + r0] = (float)sqrt(n2x / (double)(TLEN - 1));
        f[2 * NROWS + r0] = sqx;
        f[3 * NROWS + r0] = mxx;
        f[0 * NROWS + r1] = meany;
        f[1 * NROWS + r1] = (float)sqrt(n2y / (double)(TLEN - 1));
        f[2 * NROWS + r1] = sqy;
        f[3 * NROWS + r1] = mxy;
    }

    // ---- Stockham autosort radix-2 FFT (natural in, natural out) ----
    float2* src = bufA;
    float2* dst = bufB;
    #pragma unroll 1
    for (int s = 0; s < 11; s++) {
        const int l = 1 << s;
        __syncthreads();
        #pragma unroll
        for (int ti = 0; ti < 4; ti++) {
            int t = tid + 256 * ti;
            int j = t & (l - 1);
            int i = t >> s;
            float2 u = src[t];
            float2 v = src[t + HALF_T];
            float2 w = g_tw[j << (10 - s)];
            float vr = v.x * w.x - v.y * w.y;
            float vi = v.x * w.y + v.y * w.x;
            int o = t + i * l;
            dst[o]     = make_float2(u.x + vr, u.y + vi);
            dst[o + l] = make_float2(u.x - vr, u.y - vi);
        }
        float2* tmp = src; src = dst; dst = tmp;
    }
    __syncthreads();

    // unpack two real spectra, power, entropy (all fp32; F tolerance 1e-3)
    float psx = 0.f, psy = 0.f;
    float pxv[4], pyv[4];
    #pragma unroll
    for (int ki = 0; ki < 4; ki++) {
        int k = tid + 256 * ki;
        float2 Zk = src[k];
        float2 Zn = src[(TLEN - k) & (TLEN - 1)];
        float Xr = 0.5f * (Zk.x + Zn.x);
        float Xi = 0.5f * (Zk.y - Zn.y);
        float Yr = 0.5f * (Zk.y + Zn.y);
        float Yi = 0.5f * (Zn.x - Zk.x);
        float px = Xr * Xr + Xi * Xi;
        float py = Yr * Yr + Yi * Yi;
        pxv[ki] = px; pyv[ki] = py;
        psx += px; psy += py;
    }
    red2f(psx, psy, redf);
    float Sdx = (psx == 0.f) ? 1.f : psx;
    float Sdy = (psy == 0.f) ? 1.f : psy;
    float rx = 1.f / Sdx, ry = 1.f / Sdy;

    float ex = 0.f, ey = 0.f;
    #pragma unroll
    for (int ki = 0; ki < 4; ki++) {
        float p0 = pxv[ki] * rx;
        float p1 = pyv[ki] * ry;
        ex = fmaf(p0, logf(p0 + 1e-10f), ex);
        ey = fmaf(p1, logf(p1 + 1e-10f), ey);
    }
    red2f(ex, ey, redf);

    if (tid == 0) {
        float* f = g_feat + (size_t)band * 5 * NROWS;
        f[4 * NROWS + r0] = -ex;
        f[4 * NROWS + r1] = -ey;
    }
}

// ---------------- kernel 2: correlation GEMM, df chunk accumulation ----------------
// grid (4, 160). Block does 24 rows x 96 cols. 128 threads, thread tile 3x6.
#define TK 64
#define STRIDE 68
__global__ void __launch_bounds__(128) corr_kernel() {
    const int band = blockIdx.y;
    __shared__ float st[NROWS][STRIDE];   // row-major, k contiguous
    __shared__ double rinv[NROWS];
    const float* __restrict__ Xb = g_xc + (size_t)band * NROWS * TLEN;

    const int tid = threadIdx.x;          // 128
    const int tx = tid & 15;              // 0..15
    const int ty = tid >> 4;              // 0..7
    const int rbase = 24 * blockIdx.x;

    if (tid < NROWS) {
        double n2 = g_norm2[(size_t)band * NROWS + tid];
        double n = sqrt(n2);
        rinv[tid] = (n == 0.0) ? 1.0 : (1.0 / n);
    }

    float hi[3][6], lo[3][6];
    #pragma unroll
    for (int u = 0; u < 3; u++)
        #pragma unroll
        for (int w = 0; w < 6; w++) { hi[u][w] = 0.f; lo[u][w] = 0.f; }

    for (int kt = 0; kt < TLEN; kt += TK) {
        #pragma unroll
        for (int it = 0; it < 12; it++) {
            int idx = tid + 128 * it;     // 0..1535
            int r = idx >> 4, q = idx & 15;
            float4 g = *reinterpret_cast<const float4*>(Xb + (size_t)r * TLEN + kt + 4 * q);
            *reinterpret_cast<float4*>(&st[r][4 * q]) = g;
        }
        __syncthreads();

        float acc[3][6];
        #pragma unroll
        for (int u = 0; u < 3; u++)
            #pragma unroll
            for (int w = 0; w < 6; w++) acc[u][w] = 0.f;

        #pragma unroll 4
        for (int k4 = 0; k4 < 16; k4++) {
            float4 a4[3], b4[6];
            #pragma unroll
            for (int u = 0; u < 3; u++)
                a4[u] = *reinterpret_cast<const float4*>(&st[rbase + ty + 8 * u][4 * k4]);
            #pragma unroll
            for (int w = 0; w < 6; w++)
                b4[w] = *reinterpret_cast<const float4*>(&st[tx + 16 * w][4 * k4]);
            #pragma unroll
            for (int u = 0; u < 3; u++)
                #pragma unroll
                for (int w = 0; w < 6; w++) {
                    acc[u][w] = fmaf(a4[u].x, b4[w].x, acc[u][w]);
                    acc[u][w] = fmaf(a4[u].y, b4[w].y, acc[u][w]);
                    acc[u][w] = fmaf(a4[u].z, b4[w].z, acc[u][w]);
                    acc[u][w] = fmaf(a4[u].w, b4[w].w, acc[u][w]);
                }
        }
        __syncthreads();

        // compensated fp32 accumulation of the chunk sums (error ~2^-48, fp32 pipe)
        #pragma unroll
        for (int u = 0; u < 3; u++)
            #pragma unroll
            for (int w = 0; w < 6; w++) twosum_acc(hi[u][w], lo[u][w], acc[u][w]);
    }

    float* __restrict__ Cb = g_C + (size_t)band * NROWS * NROWS;
    #pragma unroll
    for (int u = 0; u < 3; u++) {
        int r = rbase + ty + 8 * u;
        double ri = rinv[r];
        #pragma unroll
        for (int w = 0; w < 6; w++) {
            int c = tx + 16 * w;
            double val = ((double)hi[u][w] + (double)lo[u][w]) * ri * rinv[c];
            Cb[r * NROWS + c] = (r == c) ? 0.f : (float)val;
        }
    }
}

// ---------------- kernel 3: radix-select quantile + mask + graph props + MLP ----------------
// grid 160, block 1024
__global__ void post_kernel(const int* __restrict__ community,
                            const float* __restrict__ W1, const float* __restrict__ b1,
                            const float* __restrict__ W2, const float* __restrict__ b2,
                            float* __restrict__ outA, float* __restrict__ outF) {
    __shared__ unsigned tril[NTRIL];
    __shared__ unsigned hist[256];
    __shared__ unsigned s_sel[2];
    __shared__ unsigned bits[NROWS][3];
    __shared__ float degf[NROWS];
    __shared__ int comm[NROWS];
    __shared__ float red[32];
    __shared__ float feat11[11];
    __shared__ float h[32];
    __shared__ float sprops[6];
    __shared__ float s_thr;

    const int band = blockIdx.x;
    const int tid = threadIdx.x;
    const int lane = tid & 31;
    const float* __restrict__ Cb = g_C + (size_t)band * NROWS * NROWS;
    float* __restrict__ Ao = outA + (size_t)band * NROWS * NROWS;

    // load |C| lower triangle as monotone uint bits
    for (int idx = tid; idx < NROWS * NROWS; idx += 1024) {
        int i = idx / NROWS, j = idx - i * NROWS;
        if (j < i) tril[i * (i - 1) / 2 + j] = __float_as_uint(fabsf(Cb[idx]));
    }
    if (tid < NROWS) comm[tid] = community[tid];
    __syncthreads();

    // ---- exact radix select for ranks 3647 and 3648 (0-based ascending) ----
    unsigned selval[2];
    #pragma unroll 1
    for (int sidx = 0; sidx < 2; sidx++) {
        int rem = 3647 + sidx;
        unsigned prefix = 0;
        #pragma unroll 1
        for (int shift = 24; shift >= 0; shift -= 8) {
            for (int i = tid; i < 256; i += 1024) hist[i] = 0;
            __syncthreads();
            unsigned pmask = (shift == 24) ? 0u : (0xFFFFFFFFu << (shift + 8));
            #pragma unroll 1
            for (int i = tid; i < NTRIL; i += 1024) {
                unsigned v = tril[i];
                if ((v & pmask) == prefix) atomicAdd(&hist[(v >> shift) & 255u], 1u);
            }
            __syncthreads();
            if (tid < 32) {
                int base = lane * 8;
                unsigned c[8]; unsigned mysum = 0;
                #pragma unroll
                for (int q = 0; q < 8; q++) { c[q] = hist[base + q]; mysum += c[q]; }
                unsigned incl = mysum;
                #pragma unroll
                for (int o = 1; o < 32; o <<= 1) {
                    unsigned t = __shfl_up_sync(0xffffffffu, incl, o);
                    if (lane >= o) incl += t;
                }
                unsigned excl = incl - mysum;
                bool has = ((unsigned)rem >= excl) && ((unsigned)rem < incl);
                unsigned ball = __ballot_sync(0xffffffffu, has);
                int owner = __ffs(ball) - 1;
                if (lane == owner) {
                    unsigned run = excl;
                    int bucket = 0; unsigned nr = 0;
                    #pragma unroll
                    for (int q = 0; q < 8; q++) {
                        if ((unsigned)rem >= run && (unsigned)rem < run + c[q]) {
                            bucket = base + q; nr = (unsigned)rem - run;
                        }
                        run += c[q];
                    }
                    s_sel[0] = (unsigned)bucket; s_sel[1] = nr;
                }
            }
            __syncthreads();
            prefix |= s_sel[0] << shift;
            rem = (int)s_sel[1];
            __syncthreads();
        }
        selval[sidx] = prefix;
    }
    if (tid == 0) {
        float a = __uint_as_float(selval[0]);
        float bq = __uint_as_float(selval[1]);
        double pos = 0.8 * (double)(NTRIL - 1);     // 3647.2
        double fr = pos - (double)((int)pos);
        s_thr = (float)((double)a + fr * ((double)bq - (double)a));
    }
    __syncthreads();
    const float thr = s_thr;

    // ---- A write (all 1024 threads) ----
    #pragma unroll 1
    for (int idx = tid; idx < NROWS * NROWS; idx += 1024) {
        int row = idx / NROWS, col = idx - row * NROWS;
        float c = Cb[idx];
        bool keep = (fabsf(c) >= thr) && (row != col);
        Ao[idx] = keep ? c : 0.f;
    }

    // ---- adjacency bitmasks + degree ----
    int mydeg = 0;
    if (tid < NROWS) {
        unsigned b0 = 0, b1w = 0, b2w = 0;
        const float* crow = Cb + tid * NROWS;
        #pragma unroll 4
        for (int j = 0; j < NROWS; j++) {
            float c = crow[j];
            bool keep = (fabsf(c) >= thr) && (j != tid);
            if (keep) {
                mydeg++;
                if (j < 32) b0 |= 1u << j;
                else if (j < 64) b1w |= 1u << (j - 32);
                else b2w |= 1u << (j - 64);
            }
        }
        bits[tid][0] = b0; bits[tid][1] = b1w; bits[tid][2] = b2w;
        degf[tid] = (float)mydeg;
    }
    __syncthreads();

    float degsum = blockReduceSum(tid < NROWS ? (float)mydeg : 0.f, red);
    float ne = 0.5f * degsum;

    float cnt = 0.f;
    if (tid < NROWS) {
        unsigned r0 = bits[tid][0], r1 = bits[tid][1], r2 = bits[tid][2];
        int c6 = 0;
        #pragma unroll 1
        for (int w = 0; w < 3; w++) {
            unsigned mw = bits[tid][w];
            while (mw) {
                int j = __ffs(mw) - 1 + 32 * w;
                mw &= mw - 1;
                c6 += __popc(r0 & bits[j][0]) + __popc(r1 & bits[j][1]) + __popc(r2 & bits[j][2]);
            }
        }
        cnt = (float)c6;
    }
    float tri6 = blockReduceSum(cnt, red);
    float tri = tri6 / 6.0f;

    float pp = (tid < NROWS) ? ((float)mydeg * ((float)mydeg - 1.0f)) : 0.f;
    float poss = blockReduceSum(pp, red) * 0.5f;

    float m2 = 2.0f * ne;
    float m2s = (m2 > 0.f) ? m2 : 1.0f;
    float macc = 0.f;
    if (tid < NROWS) {
        int ci = comm[tid];
        float di = (float)mydeg;
        #pragma unroll 2
        for (int j = 0; j < NROWS; j++) {
            if (j != tid && comm[j] == ci) {
                float bij = (float)((bits[tid][j >> 5] >> (j & 31)) & 1u);
                macc += bij - di * degf[j] / m2s;
            }
        }
    }
    float modsum = blockReduceSum(macc, red);
    float mod = (m2 > 0.f) ? (modsum / m2s) : 0.f;

    if (tid < 5) {
        const float* f = g_feat + (size_t)band * 5 * NROWS + tid * NROWS;
        float sm = 0.f;
        for (int r = 0; r < NROWS; r++) sm += f[r];
        feat11[tid] = sm / (float)NROWS;
    }
    if (tid == 0) {
        float n = (float)NROWS;
        sprops[0] = ne;
        sprops[1] = ne / (n * (n - 1.0f) * 0.5f);
        sprops[2] = degsum / n;
        sprops[3] = (poss > 0.f) ? (tri / poss) : 0.f;
        sprops[4] = (n + 2.0f * ne) / (n * (n - 1.0f));
        sprops[5] = mod;
    }
    __syncthreads();
    if (tid < 6) feat11[5 + tid] = sprops[tid];
    __syncthreads();

    if (tid < 32) {
        float acc = b1[tid];
        #pragma unroll
        for (int k = 0; k < 11; k++) acc = fmaf(feat11[k], W1[tid * 11 + k], acc);
        h[tid] = fmaxf(acc, 0.f);
    }
    __syncthreads();
    if (tid < 64) {
        float acc = b2[tid];
        #pragma unroll
        for (int k = 0; k < 32; k++) acc = fmaf(h[k], W2[tid * 32 + k], acc);
        outF[(size_t)band * 64 + tid] = acc;
    }
}

// ---------------- launch ----------------
extern "C" void kernel_launch(void* const* d_in, const int* in_sizes, int n_in,
                              void* d_out, int out_size) {
    const float* wc        = (const float*)d_in[0];
    const int*   community = (const int*)d_in[2];
    const float* W1        = (const float*)d_in[3];
    const float* b1        = (const float*)d_in[4];
    const float* W2        = (const float*)d_in[5];
    const float* b2        = (const float*)d_in[6];

    float* out = (float*)d_out;
    float* outA = out;                                   // 32*5*96*96
    float* outF = out + (size_t)NBANDS * NROWS * NROWS;  // 32*5*64

    init_tw_kernel<<<4, 256>>>();
    dim3 gS(NROWS / 2, NBANDS);
    stats_fft_kernel<<<gS, 256>>>(wc);
    dim3 gC(4, NBANDS);
    corr_kernel<<<gC, 128>>>();
    post_kernel<<<NBANDS, 1024>>>(community, W1, b1, W2, b2, outA, outF);
}